// round 1
// baseline (speedup 1.0000x reference)
#include <cuda_runtime.h>

#define B_SZ   16384
#define NL     131072
#define S_DIM  7
#define NCLS   20
#define NCELLS (B_SZ * S_DIM * S_DIM)   // 802816
#define NTOT   (NCELLS + NL)            // 933888
#define THREADS 256

__device__ double g_acc;

__global__ void init_kernel() {
    g_acc = 0.0;
}

__device__ __forceinline__ float iou_pair(float ax, float ay, float aw, float ah,
                                          float gx, float gy, float gw, float gh) {
    float ax1 = ax - aw * 0.5f, ax2 = ax + aw * 0.5f;
    float ay1 = ay - ah * 0.5f, ay2 = ay + ah * 0.5f;
    float gx1 = gx - gw * 0.5f, gx2 = gx + gw * 0.5f;
    float gy1 = gy - gh * 0.5f, gy2 = gy + gh * 0.5f;
    float iw = fmaxf(0.0f, fminf(ax2, gx2) - fmaxf(ax1, gx1));
    float ih = fmaxf(0.0f, fminf(ay2, gy2) - fmaxf(ay1, gy1));
    float inter = iw * ih;
    float uni = aw * ah + gw * gh - inter;
    return inter / (uni + 1e-6f);
}

__global__ void __launch_bounds__(THREADS)
yolo_loss_kernel(const float* __restrict__ out, const float* __restrict__ labels) {
    int tid = blockIdx.x * blockDim.x + threadIdx.x;
    float local = 0.0f;

    if (tid < NCELLS) {
        // no-object term: channels 20,21 of every cell, weight 0.5
        const float2 v = *reinterpret_cast<const float2*>(out + (size_t)tid * 30 + 20);
        local = 0.5f * (v.x * v.x + v.y * v.y);
    } else {
        int i = tid - NCELLS;
        if (i < NL) {
            const float* L = labels + (size_t)i * 6;
            float bf = L[0], cf = L[1];
            float gx = L[2], gy = L[3], gw = L[4], gh = L[5];
            int b = (int)bf;
            int c = (int)cf;
            float rowf = floorf(gx * 7.0f);
            float colf = floorf(gy * 7.0f);
            int row = (int)rowf, col = (int)colf;

            const float* p = out + ((size_t)b * 49 + (size_t)(row * 7 + col)) * 30;
            float pv[30];
            #pragma unroll
            for (int k = 0; k < 30; k++) pv[k] = __ldg(p + k);

            // class loss
            float cls = 0.0f;
            #pragma unroll
            for (int k = 0; k < NCLS; k++) {
                float d = pv[k] - (k == c ? 1.0f : 0.0f);
                cls += d * d;
            }

            // boxes -> global coords
            const float inv_s = 1.0f / 7.0f;
            float a1x = (rowf + pv[22]) * inv_s;
            float a1y = (colf + pv[23]) * inv_s;
            float a1w = pv[24], a1h = pv[25];
            float a2x = (rowf + pv[26]) * inv_s;
            float a2y = (colf + pv[27]) * inv_s;
            float a2w = pv[28], a2h = pv[29];

            float iou1 = iou_pair(a1x, a1y, a1w, a1h, gx, gy, gw, gh);
            float iou2 = iou_pair(a2x, a2y, a2w, a2h, gx, gy, gw, gh);
            bool use1 = (iou1 >= iou2);

            float gcx = gx * 7.0f - rowf;
            float gcy = gy * 7.0f - colf;

            float px = use1 ? pv[22] : pv[26];
            float py = use1 ? pv[23] : pv[27];
            float pw = use1 ? pv[24] : pv[28];
            float ph = use1 ? pv[25] : pv[29];

            const float eps = 1e-6f;
            float dx = px - gcx;
            float dy = py - gcy;
            float dw = sqrtf(pw + eps) - sqrtf(gw + eps);
            float dh = sqrtf(ph + eps) - sqrtf(gh + eps);
            float coor = 5.0f * (dx * dx + dy * dy + dw * dw + dh * dh);

            float cp = use1 ? pv[20] : pv[21];
            float ct = use1 ? iou1 : iou2;
            float cd = cp - ct;
            float conf = cd * cd - 0.5f * cp * cp;

            local = cls + coor + conf;
        }
    }

    // block reduction: warp shuffles + shared, then one double atomic per block
    #pragma unroll
    for (int o = 16; o > 0; o >>= 1)
        local += __shfl_down_sync(0xffffffffu, local, o);

    __shared__ float wsum[THREADS / 32];
    int lane = threadIdx.x & 31;
    int wid = threadIdx.x >> 5;
    if (lane == 0) wsum[wid] = local;
    __syncthreads();

    if (wid == 0) {
        float v = (lane < THREADS / 32) ? wsum[lane] : 0.0f;
        #pragma unroll
        for (int o = 4; o > 0; o >>= 1)
            v += __shfl_down_sync(0xffffffffu, v, o);
        if (lane == 0)
            atomicAdd(&g_acc, (double)v);
    }
}

__global__ void finalize_kernel(float* out) {
    out[0] = (float)(g_acc / (double)B_SZ);
}

extern "C" void kernel_launch(void* const* d_in, const int* in_sizes, int n_in,
                              void* d_out, int out_size) {
    const float* output = (const float*)d_in[0];
    const float* labels = (const float*)d_in[1];
    float* out = (float*)d_out;

    init_kernel<<<1, 1>>>();
    int blocks = (NTOT + THREADS - 1) / THREADS;   // 3648
    yolo_loss_kernel<<<blocks, THREADS>>>(output, labels);
    finalize_kernel<<<1, 1>>>(out);
}

// round 2
// speedup vs baseline: 1.2733x; 1.2733x over previous
#include <cuda_runtime.h>

#define B_SZ   16384
#define NL     131072
#define NCELLS (B_SZ * 49)              // 802816
#define NTOT   (NCELLS + NL)            // 933888
#define THREADS 256
#define NBLOCKS ((NTOT + THREADS - 1) / THREADS)   // 3648
#define NCLS   20

__device__ double       g_acc   = 0.0;
__device__ unsigned int g_count = 0;

__device__ __forceinline__ float iou_pair(float ax, float ay, float aw, float ah,
                                          float gx, float gy, float gw, float gh) {
    float ax1 = ax - aw * 0.5f, ax2 = ax + aw * 0.5f;
    float ay1 = ay - ah * 0.5f, ay2 = ay + ah * 0.5f;
    float gx1 = gx - gw * 0.5f, gx2 = gx + gw * 0.5f;
    float gy1 = gy - gh * 0.5f, gy2 = gy + gh * 0.5f;
    float iw = fmaxf(0.0f, fminf(ax2, gx2) - fmaxf(ax1, gx1));
    float ih = fmaxf(0.0f, fminf(ay2, gy2) - fmaxf(ay1, gy1));
    float inter = iw * ih;
    float uni = aw * ah + gw * gh - inter;
    return inter / (uni + 1e-6f);
}

__global__ void __launch_bounds__(THREADS)
yolo_loss_kernel(const float* __restrict__ out, const float* __restrict__ labels,
                 float* __restrict__ result) {
    int tid = blockIdx.x * blockDim.x + threadIdx.x;
    float local = 0.0f;

    if (tid < NCELLS) {
        // no-object term: channels 20,21 of every cell, weight 0.5
        // byte offset (120*tid + 80) is 8B-aligned -> single float2 load, 1 sector
        const float2 v = *reinterpret_cast<const float2*>(out + (size_t)tid * 30 + 20);
        local = 0.5f * (v.x * v.x + v.y * v.y);
    } else if (tid - NCELLS < NL) {
        int i = tid - NCELLS;
        const float2* Lp = reinterpret_cast<const float2*>(labels + (size_t)i * 6);
        float2 l0 = __ldg(Lp + 0);   // b, cls
        float2 l1 = __ldg(Lp + 1);   // gx, gy
        float2 l2 = __ldg(Lp + 2);   // gw, gh
        int b = (int)l0.x;
        int c = (int)l0.y;
        float gx = l1.x, gy = l1.y, gw = l2.x, gh = l2.y;

        float rowf = floorf(gx * 7.0f);
        float colf = floorf(gy * 7.0f);
        int row = (int)rowf, col = (int)colf;

        // p is 120B-strided -> 8B aligned: gather as 15 float2 loads
        const float2* p2 = reinterpret_cast<const float2*>(
            out + ((size_t)b * 49 + (size_t)(row * 7 + col)) * 30);
        float pv[30];
        #pragma unroll
        for (int k = 0; k < 15; k++) {
            float2 v = __ldg(p2 + k);
            pv[2 * k]     = v.x;
            pv[2 * k + 1] = v.y;
        }

        // class loss
        float cls = 0.0f;
        #pragma unroll
        for (int k = 0; k < NCLS; k++) {
            float d = pv[k] - (k == c ? 1.0f : 0.0f);
            cls += d * d;
        }

        // boxes -> global coords
        const float inv_s = 1.0f / 7.0f;
        float iou1 = iou_pair((rowf + pv[22]) * inv_s, (colf + pv[23]) * inv_s,
                              pv[24], pv[25], gx, gy, gw, gh);
        float iou2 = iou_pair((rowf + pv[26]) * inv_s, (colf + pv[27]) * inv_s,
                              pv[28], pv[29], gx, gy, gw, gh);
        bool use1 = (iou1 >= iou2);

        float gcx = gx * 7.0f - rowf;
        float gcy = gy * 7.0f - colf;

        float px = use1 ? pv[22] : pv[26];
        float py = use1 ? pv[23] : pv[27];
        float pw = use1 ? pv[24] : pv[28];
        float ph = use1 ? pv[25] : pv[29];

        const float eps = 1e-6f;
        float dx = px - gcx;
        float dy = py - gcy;
        float dw = sqrtf(pw + eps) - sqrtf(gw + eps);
        float dh = sqrtf(ph + eps) - sqrtf(gh + eps);
        float coor = 5.0f * (dx * dx + dy * dy + dw * dw + dh * dh);

        float cp = use1 ? pv[20] : pv[21];
        float ct = use1 ? iou1 : iou2;
        float cd = cp - ct;
        float conf = cd * cd - 0.5f * cp * cp;

        local = cls + coor + conf;
    }

    // block reduction: warp shuffles + shared
    #pragma unroll
    for (int o = 16; o > 0; o >>= 1)
        local += __shfl_down_sync(0xffffffffu, local, o);

    __shared__ float wsum[THREADS / 32];
    int lane = threadIdx.x & 31;
    int wid = threadIdx.x >> 5;
    if (lane == 0) wsum[wid] = local;
    __syncthreads();

    if (wid == 0) {
        float v = (lane < THREADS / 32) ? wsum[lane] : 0.0f;
        #pragma unroll
        for (int o = 4; o > 0; o >>= 1)
            v += __shfl_down_sync(0xffffffffu, v, o);
        if (lane == 0) {
            atomicAdd(&g_acc, (double)v);
            __threadfence();
            unsigned t = atomicAdd(&g_count, 1u);
            if (t == (unsigned)(gridDim.x - 1)) {
                // last block: publish result and reset state for next replay
                result[0] = (float)(g_acc / (double)B_SZ);
                g_acc = 0.0;
                g_count = 0u;
            }
        }
    }
}

extern "C" void kernel_launch(void* const* d_in, const int* in_sizes, int n_in,
                              void* d_out, int out_size) {
    const float* output = (const float*)d_in[0];
    const float* labels = (const float*)d_in[1];
    float* out = (float*)d_out;

    yolo_loss_kernel<<<NBLOCKS, THREADS>>>(output, labels, out);
}

// round 3
// speedup vs baseline: 1.8013x; 1.4147x over previous
#include <cuda_runtime.h>

#define B_SZ    16384
#define NL      131072
#define NCELLS  (B_SZ * 49)            // 802816
#define THREADS 256
#define CELL_BLOCKS 448                // 448*256 = 114688 threads, 7 cells each
#define CELL_THREADS (CELL_BLOCKS * THREADS)   // 114688
#define LABEL_BLOCKS 512               // 512*256 = 131072 = NL, 1 label each
#define NBLOCKS (CELL_BLOCKS + LABEL_BLOCKS)   // 960
#define NCLS    20

__device__ double       g_acc   = 0.0;
__device__ unsigned int g_count = 0;

__device__ __forceinline__ float iou_pair(float ax, float ay, float aw, float ah,
                                          float gx, float gy, float gw, float gh) {
    float ax1 = ax - aw * 0.5f, ax2 = ax + aw * 0.5f;
    float ay1 = ay - ah * 0.5f, ay2 = ay + ah * 0.5f;
    float gx1 = gx - gw * 0.5f, gx2 = gx + gw * 0.5f;
    float gy1 = gy - gh * 0.5f, gy2 = gy + gh * 0.5f;
    float iw = fmaxf(0.0f, fminf(ax2, gx2) - fmaxf(ax1, gx1));
    float ih = fmaxf(0.0f, fminf(ay2, gy2) - fmaxf(ay1, gy1));
    float inter = iw * ih;
    float uni = aw * ah + gw * gh - inter;
    return inter / (uni + 1e-6f);
}

__global__ void __launch_bounds__(THREADS)
yolo_loss_kernel(const float* __restrict__ out, const float* __restrict__ labels,
                 float* __restrict__ result) {
    float local = 0.0f;

    if (blockIdx.x < CELL_BLOCKS) {
        // ---- no-object term: 7 independent strided float2 loads per thread ----
        int base = blockIdx.x * THREADS + threadIdx.x;
        float2 v[7];
        #pragma unroll
        for (int k = 0; k < 7; k++) {
            int cell = base + k * CELL_THREADS;
            v[k] = *reinterpret_cast<const float2*>(out + (size_t)cell * 30 + 20);
        }
        #pragma unroll
        for (int k = 0; k < 7; k++)
            local += v[k].x * v[k].x + v[k].y * v[k].y;
        local *= 0.5f;
    } else {
        // ---- per-label term: 1 label per thread ----
        int i = (blockIdx.x - CELL_BLOCKS) * THREADS + threadIdx.x;   // < 131072 always
        const float2* Lp = reinterpret_cast<const float2*>(labels + (size_t)i * 6);
        float2 l0 = __ldg(Lp + 0);   // b, cls
        float2 l1 = __ldg(Lp + 1);   // gx, gy
        float2 l2 = __ldg(Lp + 2);   // gw, gh
        int b = (int)l0.x;
        int c = (int)l0.y;
        float gx = l1.x, gy = l1.y, gw = l2.x, gh = l2.y;

        float rowf = floorf(gx * 7.0f);
        float colf = floorf(gy * 7.0f);
        int row = (int)rowf, col = (int)colf;

        const float2* p2 = reinterpret_cast<const float2*>(
            out + ((size_t)b * 49 + (size_t)(row * 7 + col)) * 30);
        float pv[30];
        #pragma unroll
        for (int k = 0; k < 15; k++) {
            float2 v = __ldg(p2 + k);
            pv[2 * k]     = v.x;
            pv[2 * k + 1] = v.y;
        }

        // class loss
        float cls = 0.0f;
        #pragma unroll
        for (int k = 0; k < NCLS; k++) {
            float d = pv[k] - (k == c ? 1.0f : 0.0f);
            cls += d * d;
        }

        const float inv_s = 1.0f / 7.0f;
        float iou1 = iou_pair((rowf + pv[22]) * inv_s, (colf + pv[23]) * inv_s,
                              pv[24], pv[25], gx, gy, gw, gh);
        float iou2 = iou_pair((rowf + pv[26]) * inv_s, (colf + pv[27]) * inv_s,
                              pv[28], pv[29], gx, gy, gw, gh);
        bool use1 = (iou1 >= iou2);

        float gcx = gx * 7.0f - rowf;
        float gcy = gy * 7.0f - colf;

        float px = use1 ? pv[22] : pv[26];
        float py = use1 ? pv[23] : pv[27];
        float pw = use1 ? pv[24] : pv[28];
        float ph = use1 ? pv[25] : pv[29];

        const float eps = 1e-6f;
        float dx = px - gcx;
        float dy = py - gcy;
        float dw = sqrtf(pw + eps) - sqrtf(gw + eps);
        float dh = sqrtf(ph + eps) - sqrtf(gh + eps);
        float coor = 5.0f * (dx * dx + dy * dy + dw * dw + dh * dh);

        float cp = use1 ? pv[20] : pv[21];
        float ct = use1 ? iou1 : iou2;
        float cd = cp - ct;
        float conf = cd * cd - 0.5f * cp * cp;

        local = cls + coor + conf;
    }

    // block reduction: warp shuffles + shared
    #pragma unroll
    for (int o = 16; o > 0; o >>= 1)
        local += __shfl_down_sync(0xffffffffu, local, o);

    __shared__ float wsum[THREADS / 32];
    int lane = threadIdx.x & 31;
    int wid = threadIdx.x >> 5;
    if (lane == 0) wsum[wid] = local;
    __syncthreads();

    if (wid == 0) {
        float v = (lane < THREADS / 32) ? wsum[lane] : 0.0f;
        #pragma unroll
        for (int o = 4; o > 0; o >>= 1)
            v += __shfl_down_sync(0xffffffffu, v, o);
        if (lane == 0) {
            atomicAdd(&g_acc, (double)v);
            __threadfence();
            unsigned t = atomicAdd(&g_count, 1u);
            if (t == (unsigned)(gridDim.x - 1)) {
                // last block: publish result and reset state for next replay
                result[0] = (float)(g_acc / (double)B_SZ);
                g_acc = 0.0;
                g_count = 0u;
            }
        }
    }
}

extern "C" void kernel_launch(void* const* d_in, const int* in_sizes, int n_in,
                              void* d_out, int out_size) {
    const float* output = (const float*)d_in[0];
    const float* labels = (const float*)d_in[1];
    float* out = (float*)d_out;

    yolo_loss_kernel<<<NBLOCKS, THREADS>>>(output, labels, out);
}